// round 5
// baseline (speedup 1.0000x reference)
#include <cuda_runtime.h>
#include <cstdint>

#define NE 32
#define TOPK 4
#define HDIM 1024
#define IDIM 1024
#define NT 2048
#define N2I 2048
#define ALPHA 1.702f
#define LIMIT 7.0f

// ---------------- device scratch ----------------
__device__ int   g_cnt[NE];
__device__ int   g_off[NE];
__device__ int   g_list[NE * NT];
__device__ float g_wgt[NE * NT];
__device__ float g_xtf[(size_t)NT * HDIM];          // x pre-rounded to tf32 (8 MB)
__device__ float g_act[(size_t)TOPK * NT * IDIM];   // activations, pre-rounded tf32 (32 MB)

// ---------------- helpers ----------------
__device__ __forceinline__ uint32_t f2tf(float f) {
    uint32_t u;
    asm("cvt.rna.tf32.f32 %0, %1;" : "=r"(u) : "f"(f));
    return u;
}

__device__ __forceinline__ void mma_tf32(float* c, const uint32_t* a, const uint32_t* b) {
    asm volatile(
        "mma.sync.aligned.m16n8k8.row.col.f32.tf32.tf32.f32 "
        "{%0,%1,%2,%3}, {%4,%5,%6,%7}, {%8,%9}, {%0,%1,%2,%3};"
        : "+f"(c[0]), "+f"(c[1]), "+f"(c[2]), "+f"(c[3])
        : "r"(a[0]), "r"(a[1]), "r"(a[2]), "r"(a[3]), "r"(b[0]), "r"(b[1]));
}

__device__ __forceinline__ void cp16a(uint32_t dst, const void* src, int sz) {
    asm volatile("cp.async.ca.shared.global [%0], [%1], 16, %2;"
                 :: "r"(dst), "l"(src), "r"(sz));
}
__device__ __forceinline__ void cp16b(uint32_t dst, const void* src) {
    asm volatile("cp.async.cg.shared.global [%0], [%1], 16;"
                 :: "r"(dst), "l"(src));
}
#define CP_COMMIT asm volatile("cp.async.commit_group;")
#define CP_WAIT1  asm volatile("cp.async.wait_group 1;" ::: "memory")
#define CP_WAIT0  asm volatile("cp.async.wait_group 0;" ::: "memory")

// ---------------- kernel 0: zero output + counters ----------------
__global__ void zero_kernel(float* __restrict__ routed) {
    int i = blockIdx.x * blockDim.x + threadIdx.x;
    if (i < NT * HDIM) routed[i] = 0.0f;
    if (blockIdx.x == 0 && threadIdx.x < NE) g_cnt[threadIdx.x] = 0;
}

// ---------------- kernel 1: router (8 tokens per block, warp per token) ---
// also writes g_xtf (tf32-rounded copy of x)
__global__ __launch_bounds__(256) void router_kernel(
    const float* __restrict__ x,
    const float* __restrict__ rw,
    const float* __restrict__ rb,
    float* __restrict__ scores) {

    int warp = threadIdx.x >> 5, lane = threadIdx.x & 31;
    int t = blockIdx.x * 8 + warp;

    // load token row into registers; write tf32 copy
    float xv[32];
    #pragma unroll
    for (int i = 0; i < 32; i++) {
        float v = x[(size_t)t * HDIM + i * 32 + lane];
        xv[i] = v;
        g_xtf[(size_t)t * HDIM + i * 32 + lane] = __uint_as_float(f2tf(v));
    }

    // 32 expert logits
    float logit[NE];  // only lane 0 keeps the full set after reduce
    #pragma unroll 4
    for (int e = 0; e < NE; e++) {
        const float* wr = rw + (size_t)e * HDIM;
        float acc = 0.0f;
        #pragma unroll
        for (int i = 0; i < 32; i++) acc += xv[i] * wr[i * 32 + lane];
        #pragma unroll
        for (int s = 16; s > 0; s >>= 1) acc += __shfl_down_sync(0xffffffffu, acc, s);
        logit[e] = acc;  // valid on lane 0
    }

    // zero the scores row (all lanes), then lane 0 overwrites top-4
    scores[(size_t)t * NE + lane] = 0.0f;
    __syncwarp();

    if (lane == 0) {
        float lg[NE];
        #pragma unroll
        for (int e = 0; e < NE; e++) lg[e] = logit[e] + rb[e];
        int   sidx[TOPK];
        float swt[TOPK];
        bool used[NE];
        #pragma unroll
        for (int e = 0; e < NE; e++) used[e] = false;
        for (int k = 0; k < TOPK; k++) {
            float best = -1e30f; int bi = 0;
            for (int e = 0; e < NE; e++)
                if (!used[e] && lg[e] > best) { best = lg[e]; bi = e; }
            used[bi] = true; sidx[k] = bi; swt[k] = best;
        }
        float m = swt[0], s = 0.0f;
        for (int k = 0; k < TOPK; k++) { swt[k] = expf(swt[k] - m); s += swt[k]; }
        float inv = 1.0f / s;
        for (int k = 0; k < TOPK; k++) {
            swt[k] *= inv;
            int e = sidx[k];
            int pos = atomicAdd(&g_cnt[e], 1);
            g_list[e * NT + pos] = t;
            g_wgt[e * NT + pos]  = swt[k];
            scores[(size_t)t * NE + e] = swt[k];
        }
    }
}

// ---------------- kernel 2: exclusive scan ----------------
__global__ void scan_kernel() {
    if (threadIdx.x == 0) {
        int s = 0;
        for (int e = 0; e < NE; e++) { g_off[e] = s; s += g_cnt[e]; }
    }
}

// ---------------- kernel 3: gate_up GEMM + activation ----------------
// BM=128, BN=128, BK=16, 128 threads (4 warps, 2x2, warp tile 64x64)
__global__ __launch_bounds__(128, 3) void gateup_kernel(
    const float* __restrict__ gup,
    const float* __restrict__ gub) {

    int e = blockIdx.z, mt = blockIdx.y, nt = blockIdx.x;
    int cnt = g_cnt[e];
    if (mt * 128 >= cnt) return;
    int off = g_off[e];

    __shared__ float sA[2][128][20];
    __shared__ float sB[2][16][132];

    int tid = threadIdx.x;
    int r = mt * 128 + tid;
    int tok = (r < cnt) ? g_list[e * NT + r] : -1;
    int apred = (tok >= 0) ? 16 : 0;
    const float* aSrc = g_xtf + (size_t)(tok >= 0 ? tok : 0) * HDIM;
    const float* bSrc = gup + (size_t)e * HDIM * N2I + nt * 128;

    uint32_t aBase = (uint32_t)__cvta_generic_to_shared(&sA[0][0][0]) + tid * 80;
    uint32_t bBase = (uint32_t)__cvta_generic_to_shared(&sB[0][0][0]);
    const uint32_t A_STAGE = 128 * 20 * 4;
    const uint32_t B_STAGE = 16 * 132 * 4;

    auto issue = [&](int s, int k0) {
        uint32_t ad = aBase + s * A_STAGE;
        const float* as = aSrc + k0;
        #pragma unroll
        for (int j = 0; j < 4; j++) cp16a(ad + j * 16, as + j * 4, apred);
        #pragma unroll
        for (int j = 0; j < 4; j++) {
            int idx = tid + j * 128;
            int k = idx >> 5, c = (idx & 31) * 4;
            cp16b(bBase + s * B_STAGE + k * 528 + c * 4,
                  bSrc + (size_t)(k0 + k) * N2I + c);
        }
    };

    issue(0, 0);  CP_COMMIT;
    issue(1, 16); CP_COMMIT;

    int warp = tid >> 5, lane = tid & 31;
    int wm = warp & 1, wn = warp >> 1;
    int r0 = lane >> 2, c0 = lane & 3;

    float acc[4][8][4] = {};

    CP_WAIT1;
    __syncthreads();

    for (int kt = 0; kt < 64; kt++) {
        int s = kt & 1;
        #pragma unroll
        for (int kk = 0; kk < 2; kk++) {
            int kb = kk * 8;
            uint32_t a[4][4], b[8][2];
            #pragma unroll
            for (int mi = 0; mi < 4; mi++) {
                int rb = wm * 64 + mi * 16 + r0;
                // g_xtf pre-rounded: raw bits valid tf32
                a[mi][0] = __float_as_uint(sA[s][rb][kb + c0]);
                a[mi][1] = __float_as_uint(sA[s][rb + 8][kb + c0]);
                a[mi][2] = __float_as_uint(sA[s][rb][kb + c0 + 4]);
                a[mi][3] = __float_as_uint(sA[s][rb + 8][kb + c0 + 4]);
            }
            #pragma unroll
            for (int ni = 0; ni < 8; ni++) {
                int ncl = wn * 64 + ni * 8 + r0;
                b[ni][0] = f2tf(sB[s][kb + c0][ncl]);
                b[ni][1] = f2tf(sB[s][kb + c0 + 4][ncl]);
            }
            #pragma unroll
            for (int mi = 0; mi < 4; mi++)
                #pragma unroll
                for (int ni = 0; ni < 8; ni++)
                    mma_tf32(acc[mi][ni], a[mi], b[ni]);
        }
        if (kt == 63) break;
        __syncthreads();
        if (kt + 2 < 64) { issue(s, (kt + 2) * 16); CP_COMMIT; CP_WAIT1; }
        else             { CP_WAIT0; }
        __syncthreads();
    }

    // epilogue: bias + clamp + glu; store pre-rounded tf32 into g_act
    const float* gubp = gub + (size_t)e * N2I + nt * 128;
    #pragma unroll
    for (int mi = 0; mi < 4; mi++)
        #pragma unroll
        for (int ni = 0; ni < 8; ni++)
            #pragma unroll
            for (int half = 0; half < 2; half++) {
                int li = wm * 64 + mi * 16 + r0 + half * 8;
                int rr = mt * 128 + li;
                if (rr < cnt) {
                    int ln = wn * 64 + ni * 8 + c0 * 2;
                    float gate = acc[mi][ni][half * 2 + 0] + gubp[ln];
                    float up   = acc[mi][ni][half * 2 + 1] + gubp[ln + 1];
                    gate = fminf(gate, LIMIT);
                    up   = fminf(fmaxf(up, -LIMIT), LIMIT);
                    float glu = gate * (1.0f / (1.0f + __expf(-ALPHA * gate)));
                    float v = (up + 1.0f) * glu;
                    g_act[(size_t)(off + rr) * IDIM + nt * 64 + wn * 32 + ni * 4 + c0] =
                        __uint_as_float(f2tf(v));
                }
            }
}

// ---------------- kernel 4: down GEMM + weighted scatter-add ----------------
// BM=128, BN=128, BK=16, 128 threads (4 warps, 2x2, warp tile 64x64)
__global__ __launch_bounds__(128, 3) void down_kernel(
    const float* __restrict__ dw,
    const float* __restrict__ db,
    float* __restrict__ outp) {

    int e = blockIdx.z, mt = blockIdx.y, nt = blockIdx.x;
    int cnt = g_cnt[e];
    if (mt * 128 >= cnt) return;
    int off = g_off[e];

    __shared__ float sA[2][128][20];
    __shared__ float sB[2][16][132];
    __shared__ int   sTok[128];
    __shared__ float sW[128];

    int tid = threadIdx.x;
    int r = mt * 128 + tid;
    bool valid = r < cnt;
    sTok[tid] = valid ? g_list[e * NT + r] : 0;
    sW[tid]   = valid ? g_wgt[e * NT + r]  : 0.0f;

    int apred = valid ? 16 : 0;
    const float* aSrc = g_act + (size_t)(off + (valid ? r : 0)) * IDIM;
    const float* bSrc = dw + (size_t)e * IDIM * HDIM + nt * 128;

    uint32_t aBase = (uint32_t)__cvta_generic_to_shared(&sA[0][0][0]) + tid * 80;
    uint32_t bBase = (uint32_t)__cvta_generic_to_shared(&sB[0][0][0]);
    const uint32_t A_STAGE = 128 * 20 * 4;
    const uint32_t B_STAGE = 16 * 132 * 4;

    auto issue = [&](int s, int k0) {
        uint32_t ad = aBase + s * A_STAGE;
        const float* as = aSrc + k0;
        #pragma unroll
        for (int j = 0; j < 4; j++) cp16a(ad + j * 16, as + j * 4, apred);
        #pragma unroll
        for (int j = 0; j < 4; j++) {
            int idx = tid + j * 128;
            int k = idx >> 5, c = (idx & 31) * 4;
            cp16b(bBase + s * B_STAGE + k * 528 + c * 4,
                  bSrc + (size_t)(k0 + k) * HDIM + c);
        }
    };

    issue(0, 0);  CP_COMMIT;
    issue(1, 16); CP_COMMIT;

    int warp = tid >> 5, lane = tid & 31;
    int wm = warp & 1, wn = warp >> 1;
    int r0 = lane >> 2, c0 = lane & 3;

    float acc[4][8][4] = {};

    CP_WAIT1;
    __syncthreads();

    for (int kt = 0; kt < 64; kt++) {
        int s = kt & 1;
        #pragma unroll
        for (int kk = 0; kk < 2; kk++) {
            int kb = kk * 8;
            uint32_t a[4][4], b[8][2];
            #pragma unroll
            for (int mi = 0; mi < 4; mi++) {
                int rb = wm * 64 + mi * 16 + r0;
                a[mi][0] = __float_as_uint(sA[s][rb][kb + c0]);
                a[mi][1] = __float_as_uint(sA[s][rb + 8][kb + c0]);
                a[mi][2] = __float_as_uint(sA[s][rb][kb + c0 + 4]);
                a[mi][3] = __float_as_uint(sA[s][rb + 8][kb + c0 + 4]);
            }
            #pragma unroll
            for (int ni = 0; ni < 8; ni++) {
                int ncl = wn * 64 + ni * 8 + r0;
                b[ni][0] = f2tf(sB[s][kb + c0][ncl]);
                b[ni][1] = f2tf(sB[s][kb + c0 + 4][ncl]);
            }
            #pragma unroll
            for (int mi = 0; mi < 4; mi++)
                #pragma unroll
                for (int ni = 0; ni < 8; ni++)
                    mma_tf32(acc[mi][ni], a[mi], b[ni]);
        }
        if (kt == 63) break;
        __syncthreads();
        if (kt + 2 < 64) { issue(s, (kt + 2) * 16); CP_COMMIT; CP_WAIT1; }
        else             { CP_WAIT0; }
        __syncthreads();
    }

    const float* dbp = db + (size_t)e * HDIM + nt * 128;
    #pragma unroll
    for (int mi = 0; mi < 4; mi++)
        #pragma unroll
        for (int ni = 0; ni < 8; ni++)
            #pragma unroll
            for (int half = 0; half < 2; half++) {
                int li = wm * 64 + mi * 16 + r0 + half * 8;
                int rr = mt * 128 + li;
                if (rr < cnt) {
                    int tok2 = sTok[li];
                    float w  = sW[li];
                    int ln = wn * 64 + ni * 8 + c0 * 2;
                    float d0 = (acc[mi][ni][half * 2 + 0] + dbp[ln])     * w;
                    float d1 = (acc[mi][ni][half * 2 + 1] + dbp[ln + 1]) * w;
                    float* p = &outp[(size_t)tok2 * HDIM + nt * 128 + ln];
                    atomicAdd(p,     d0);
                    atomicAdd(p + 1, d1);
                }
            }
}

// ---------------- launch ----------------
extern "C" void kernel_launch(void* const* d_in, const int* in_sizes, int n_in,
                              void* d_out, int out_size) {
    const float* x   = (const float*)d_in[0];
    const float* gup = (const float*)d_in[1];
    const float* gub = (const float*)d_in[2];
    const float* dw  = (const float*)d_in[3];
    const float* db  = (const float*)d_in[4];
    const float* rw  = (const float*)d_in[5];
    const float* rb  = (const float*)d_in[6];

    float* routed = (float*)d_out;
    float* scores = (float*)d_out + (out_size - NT * NE);

    zero_kernel<<<(NT * HDIM + 1023) / 1024, 1024>>>(routed);
    router_kernel<<<NT / 8, 256>>>(x, rw, rb, scores);
    scan_kernel<<<1, 32>>>();
    gateup_kernel<<<dim3(16, 16, 32), 128>>>(gup, gub);
    down_kernel<<<dim3(8, 16, 32), 128>>>(dw, db, routed);
}

// round 17
// speedup vs baseline: 1.1277x; 1.1277x over previous
#include <cuda_runtime.h>
#include <cstdint>

#define NE 32
#define TOPK 4
#define HDIM 1024
#define IDIM 1024
#define NT 2048
#define N2I 2048
#define ALPHA 1.702f
#define LIMIT 7.0f

// ---------------- device scratch ----------------
__device__ int   g_cnt[NE];
__device__ int   g_off[NE];
__device__ int   g_list[NE * NT];
__device__ int   g_texp[NT * TOPK];
__device__ int   g_tpos[NT * TOPK];
__device__ float g_twt[NT * TOPK];
__device__ float g_xtf[(size_t)NT * HDIM];          // x, pre-rounded tf32 (rna)
__device__ float g_act[(size_t)TOPK * NT * IDIM];   // activations, pre-rounded tf32
__device__ float g_out[(size_t)TOPK * NT * HDIM];   // down results + bias (unweighted)

// ---------------- helpers ----------------
__device__ __forceinline__ uint32_t f2tf(float f) {
    uint32_t u;
    asm("cvt.rna.tf32.f32 %0, %1;" : "=r"(u) : "f"(f));
    return u;
}

__device__ __forceinline__ void mma_tf32(float* c, const uint32_t* a, const uint32_t* b) {
    asm volatile(
        "mma.sync.aligned.m16n8k8.row.col.f32.tf32.tf32.f32 "
        "{%0,%1,%2,%3}, {%4,%5,%6,%7}, {%8,%9}, {%0,%1,%2,%3};"
        : "+f"(c[0]), "+f"(c[1]), "+f"(c[2]), "+f"(c[3])
        : "r"(a[0]), "r"(a[1]), "r"(a[2]), "r"(a[3]), "r"(b[0]), "r"(b[1]));
}

__device__ __forceinline__ void cp16p(uint32_t dst, const void* src, int sz) {
    asm volatile("cp.async.ca.shared.global [%0], [%1], 16, %2;"
                 :: "r"(dst), "l"(src), "r"(sz));
}
__device__ __forceinline__ void cp16(uint32_t dst, const void* src) {
    asm volatile("cp.async.cg.shared.global [%0], [%1], 16;"
                 :: "r"(dst), "l"(src));
}
#define CP_COMMIT asm volatile("cp.async.commit_group;")
#define CP_WAIT1  asm volatile("cp.async.wait_group 1;" ::: "memory")
#define CP_WAIT0  asm volatile("cp.async.wait_group 0;" ::: "memory")

// 3-stage layout (dynamic smem)
#define A_ST 10240              // 128 rows x 20 floats
#define B_ST 8448               // 16 rows x 132 floats
#define SMEM_BYTES (3 * (A_ST + B_ST))   // 56064

// ---------------- kernel 0: zero counters ----------------
__global__ void zero_kernel() {
    if (threadIdx.x < NE) g_cnt[threadIdx.x] = 0;
}

// ---------------- kernel 1: router + tf32 copy of x ----------------
__global__ __launch_bounds__(128) void router_kernel(
    const float* __restrict__ x,
    const float* __restrict__ rw,
    const float* __restrict__ rb,
    float* __restrict__ scores) {
    int t = blockIdx.x;
    __shared__ float sx[HDIM];
    __shared__ float slog[NE];
    __shared__ int   sidx[TOPK];
    __shared__ float swt[TOPK];

    int tid = threadIdx.x;
    for (int i = tid; i < HDIM; i += 128) {
        float v = x[(size_t)t * HDIM + i];
        sx[i] = v;
        g_xtf[(size_t)t * HDIM + i] = __uint_as_float(f2tf(v));
    }
    __syncthreads();

    int w = tid >> 5, lane = tid & 31;
    for (int j = 0; j < 8; j++) {
        int e = w * 8 + j;
        const float* wr = rw + (size_t)e * HDIM;
        float acc = 0.0f;
        for (int h = lane; h < HDIM; h += 32) acc += sx[h] * wr[h];
        #pragma unroll
        for (int s = 16; s > 0; s >>= 1) acc += __shfl_down_sync(0xffffffffu, acc, s);
        if (lane == 0) slog[e] = acc + rb[e];
    }
    __syncthreads();

    if (tid == 0) {
        bool used[NE];
        #pragma unroll
        for (int e = 0; e < NE; e++) used[e] = false;
        for (int k = 0; k < TOPK; k++) {
            float best = -1e30f; int bi = 0;
            for (int e = 0; e < NE; e++)
                if (!used[e] && slog[e] > best) { best = slog[e]; bi = e; }
            used[bi] = true; sidx[k] = bi; swt[k] = best;
        }
        float m = swt[0], s = 0.0f;
        for (int k = 0; k < TOPK; k++) { swt[k] = expf(swt[k] - m); s += swt[k]; }
        float inv = 1.0f / s;
        for (int k = 0; k < TOPK; k++) {
            swt[k] *= inv;
            int e = sidx[k];
            int pos = atomicAdd(&g_cnt[e], 1);
            g_list[e * NT + pos] = t;
            g_texp[t * TOPK + k] = e;
            g_tpos[t * TOPK + k] = pos;
            g_twt[t * TOPK + k]  = swt[k];
        }
    }
    __syncthreads();

    if (tid < NE) {
        float v = 0.0f;
        #pragma unroll
        for (int k = 0; k < TOPK; k++)
            if (sidx[k] == tid) v = swt[k];
        scores[(size_t)t * NE + tid] = v;
    }
}

// ---------------- kernel 2: exclusive scan ----------------
__global__ void scan_kernel() {
    if (threadIdx.x == 0) {
        int s = 0;
        for (int e = 0; e < NE; e++) { g_off[e] = s; s += g_cnt[e]; }
    }
}

// ---------------- kernel 3: gate_up GEMM + activation ----------------
// BM=128, BN=128, BK=16, 3-stage pipeline, 128 threads (2x2 warps, 64x64 tiles)
__global__ __launch_bounds__(128, 3) void gateup_kernel(
    const float* __restrict__ gup,
    const float* __restrict__ gub) {

    int e = blockIdx.z, mt = blockIdx.y, nt = blockIdx.x;
    int cnt = g_cnt[e];
    if (mt * 128 >= cnt) return;
    int off = g_off[e];

    extern __shared__ float smem[];
    float* sA = smem;                       // 3 stages of [128][20]
    float* sB = smem + 3 * (A_ST / 4);      // 3 stages of [16][132]

    int tid = threadIdx.x;
    int r = mt * 128 + tid;
    int tok = (r < cnt) ? g_list[e * NT + r] : 0;
    int apred = (r < cnt) ? 16 : 0;
    const float* aSrc = g_xtf + (size_t)tok * HDIM;
    const float* bSrc = gup + (size_t)e * HDIM * N2I + nt * 128;

    uint32_t aBase = (uint32_t)__cvta_generic_to_shared(sA) + tid * 80;
    uint32_t bBase = (uint32_t)__cvta_generic_to_shared(sB);

    auto issue = [&](int s, int k0) {
        uint32_t ad = aBase + s * A_ST;
        const float* as = aSrc + k0;
        #pragma unroll
        for (int j = 0; j < 4; j++) cp16p(ad + j * 16, as + j * 4, apred);
        #pragma unroll
        for (int j = 0; j < 4; j++) {
            int idx = tid + j * 128;
            int k = idx >> 5, c = (idx & 31) * 4;
            cp16(bBase + s * B_ST + k * 528 + c * 4,
                 bSrc + (size_t)(k0 + k) * N2I + c);
        }
    };

    issue(0, 0);  CP_COMMIT;
    issue(1, 16); CP_COMMIT;

    int warp = tid >> 5, lane = tid & 31;
    int wm = warp & 1, wn = warp >> 1;
    int r0 = lane >> 2, c0 = lane & 3;

    float acc[4][8][4] = {};

    for (int kt = 0; kt < 64; kt++) {
        int s = kt - (kt / 3) * 3;   // kt % 3
        if (kt == 63) { CP_WAIT0; } else { CP_WAIT1; }
        __syncthreads();
        if (kt + 2 < 64) {
            int s2 = (kt + 2) - ((kt + 2) / 3) * 3;
            issue(s2, (kt + 2) * 16);
            CP_COMMIT;
        }
        const float* A = sA + s * (A_ST / 4);
        const float* B = sB + s * (B_ST / 4);
        #pragma unroll
        for (int kk = 0; kk < 2; kk++) {
            int kb = kk * 8;
            uint32_t a[4][4], b[8][2];
            #pragma unroll
            for (int mi = 0; mi < 4; mi++) {
                int rb = wm * 64 + mi * 16 + r0;
                a[mi][0] = __float_as_uint(A[rb * 20 + kb + c0]);
                a[mi][1] = __float_as_uint(A[(rb + 8) * 20 + kb + c0]);
                a[mi][2] = __float_as_uint(A[rb * 20 + kb + c0 + 4]);
                a[mi][3] = __float_as_uint(A[(rb + 8) * 20 + kb + c0 + 4]);
            }
            #pragma unroll
            for (int ni = 0; ni < 8; ni++) {
                int ncl = wn * 64 + ni * 8 + r0;
                b[ni][0] = f2tf(B[(kb + c0) * 132 + ncl]);
                b[ni][1] = f2tf(B[(kb + c0 + 4) * 132 + ncl]);
            }
            #pragma unroll
            for (int mi = 0; mi < 4; mi++)
                #pragma unroll
                for (int ni = 0; ni < 8; ni++)
                    mma_tf32(acc[mi][ni], a[mi], b[ni]);
        }
    }

    // epilogue: bias + clamp + glu; store pre-rounded tf32 into g_act
    const float* gubp = gub + (size_t)e * N2I + nt * 128;
    #pragma unroll
    for (int mi = 0; mi < 4; mi++)
        #pragma unroll
        for (int ni = 0; ni < 8; ni++)
            #pragma unroll
            for (int half = 0; half < 2; half++) {
                int li = wm * 64 + mi * 16 + r0 + half * 8;
                int rr = mt * 128 + li;
                if (rr < cnt) {
                    int ln = wn * 64 + ni * 8 + c0 * 2;
                    float gate = acc[mi][ni][half * 2 + 0] + gubp[ln];
                    float up   = acc[mi][ni][half * 2 + 1] + gubp[ln + 1];
                    gate = fminf(gate, LIMIT);
                    up   = fminf(fmaxf(up, -LIMIT), LIMIT);
                    float glu = gate * (1.0f / (1.0f + __expf(-ALPHA * gate)));
                    g_act[(size_t)(off + rr) * IDIM + nt * 64 + wn * 32 + ni * 4 + c0] =
                        __uint_as_float(f2tf((up + 1.0f) * glu));
                }
            }
}

// ---------------- kernel 4: down GEMM -> g_out (no atomics) ----------------
__global__ __launch_bounds__(128, 3) void down_kernel(
    const float* __restrict__ dw,
    const float* __restrict__ db) {

    int e = blockIdx.z, mt = blockIdx.y, nt = blockIdx.x;
    int cnt = g_cnt[e];
    if (mt * 128 >= cnt) return;
    int off = g_off[e];

    extern __shared__ float smem[];
    float* sA = smem;
    float* sB = smem + 3 * (A_ST / 4);

    int tid = threadIdx.x;
    int r = mt * 128 + tid;
    bool valid = r < cnt;
    int apred = valid ? 16 : 0;
    const float* aSrc = g_act + (size_t)(off + (valid ? r : 0)) * IDIM;
    const float* bSrc = dw + (size_t)e * IDIM * HDIM + nt * 128;

    uint32_t aBase = (uint32_t)__cvta_generic_to_shared(sA) + tid * 80;
    uint32_t bBase = (uint32_t)__cvta_generic_to_shared(sB);

    auto issue = [&](int s, int k0) {
        uint32_t ad = aBase + s * A_ST;
        const float* as = aSrc + k0;
        #pragma unroll
        for (int j = 0; j < 4; j++) cp16p(ad + j * 16, as + j * 4, apred);
        #pragma unroll
        for (int j = 0; j < 4; j++) {
            int idx = tid + j * 128;
            int k = idx >> 5, c = (idx & 31) * 4;
            cp16(bBase + s * B_ST + k * 528 + c * 4,
                 bSrc + (size_t)(k0 + k) * HDIM + c);
        }
    };

    issue(0, 0);  CP_COMMIT;
    issue(1, 16); CP_COMMIT;

    int warp = tid >> 5, lane = tid & 31;
    int wm = warp & 1, wn = warp >> 1;
    int r0 = lane >> 2, c0 = lane & 3;

    float acc[4][8][4] = {};

    for (int kt = 0; kt < 64; kt++) {
        int s = kt - (kt / 3) * 3;
        if (kt == 63) { CP_WAIT0; } else { CP_WAIT1; }
        __syncthreads();
        if (kt + 2 < 64) {
            int s2 = (kt + 2) - ((kt + 2) / 3) * 3;
            issue(s2, (kt + 2) * 16);
            CP_COMMIT;
        }
        const float* A = sA + s * (A_ST / 4);
        const float* B = sB + s * (B_ST / 4);
        #pragma unroll
        for (int kk = 0; kk < 2; kk++) {
            int kb = kk * 8;
            uint32_t a[4][4], b[8][2];
            #pragma unroll
            for (int mi = 0; mi < 4; mi++) {
                int rb = wm * 64 + mi * 16 + r0;
                a[mi][0] = __float_as_uint(A[rb * 20 + kb + c0]);
                a[mi][1] = __float_as_uint(A[(rb + 8) * 20 + kb + c0]);
                a[mi][2] = __float_as_uint(A[rb * 20 + kb + c0 + 4]);
                a[mi][3] = __float_as_uint(A[(rb + 8) * 20 + kb + c0 + 4]);
            }
            #pragma unroll
            for (int ni = 0; ni < 8; ni++) {
                int ncl = wn * 64 + ni * 8 + r0;
                b[ni][0] = f2tf(B[(kb + c0) * 132 + ncl]);
                b[ni][1] = f2tf(B[(kb + c0 + 4) * 132 + ncl]);
            }
            #pragma unroll
            for (int mi = 0; mi < 4; mi++)
                #pragma unroll
                for (int ni = 0; ni < 8; ni++)
                    mma_tf32(acc[mi][ni], a[mi], b[ni]);
        }
    }

    // epilogue: + bias, coalesced store to g_out (weight applied in gather)
    const float* dbp = db + (size_t)e * HDIM + nt * 128;
    #pragma unroll
    for (int mi = 0; mi < 4; mi++)
        #pragma unroll
        for (int ni = 0; ni < 8; ni++)
            #pragma unroll
            for (int half = 0; half < 2; half++) {
                int li = wm * 64 + mi * 16 + r0 + half * 8;
                int rr = mt * 128 + li;
                if (rr < cnt) {
                    int ln = wn * 64 + ni * 8 + c0 * 2;
                    float2 v;
                    v.x = acc[mi][ni][half * 2 + 0] + dbp[ln];
                    v.y = acc[mi][ni][half * 2 + 1] + dbp[ln + 1];
                    *(float2*)&g_out[(size_t)(off + rr) * HDIM + nt * 128 + ln] = v;
                }
            }
}

// ---------------- kernel 5: gather (weighted sum of 4 slots per token) ----
__global__ __launch_bounds__(128) void gather_kernel(float* __restrict__ routed) {
    int t = blockIdx.x, tid = threadIdx.x;
    float4 a0 = make_float4(0.f, 0.f, 0.f, 0.f), a1 = a0;
    #pragma unroll
    for (int k = 0; k < TOPK; k++) {
        int e   = g_texp[t * TOPK + k];
        int pos = g_tpos[t * TOPK + k];
        float w = g_twt[t * TOPK + k];
        const float4* p = (const float4*)&g_out[(size_t)(g_off[e] + pos) * HDIM + tid * 8];
        float4 v0 = p[0], v1 = p[1];
        a0.x += w * v0.x; a0.y += w * v0.y; a0.z += w * v0.z; a0.w += w * v0.w;
        a1.x += w * v1.x; a1.y += w * v1.y; a1.z += w * v1.z; a1.w += w * v1.w;
    }
    float4* o = (float4*)&routed[(size_t)t * HDIM + tid * 8];
    o[0] = a0; o[1] = a1;
}

// ---------------- launch ----------------
extern "C" void kernel_launch(void* const* d_in, const int* in_sizes, int n_in,
                              void* d_out, int out_size) {
    const float* x   = (const float*)d_in[0];
    const float* gup = (const float*)d_in[1];
    const float* gub = (const float*)d_in[2];
    const float* dw  = (const float*)d_in[3];
    const float* db  = (const float*)d_in[4];
    const float* rw  = (const float*)d_in[5];
    const float* rb  = (const float*)d_in[6];

    float* routed = (float*)d_out;
    float* scores = (float*)d_out + (out_size - NT * NE);

    cudaFuncSetAttribute(gateup_kernel, cudaFuncAttributeMaxDynamicSharedMemorySize, SMEM_BYTES);
    cudaFuncSetAttribute(down_kernel,   cudaFuncAttributeMaxDynamicSharedMemorySize, SMEM_BYTES);

    zero_kernel<<<1, 32>>>();
    router_kernel<<<NT, 128>>>(x, rw, rb, scores);
    scan_kernel<<<1, 32>>>();
    gateup_kernel<<<dim3(16, 16, 32), 128, SMEM_BYTES>>>(gup, gub);
    down_kernel<<<dim3(8, 16, 32), 128, SMEM_BYTES>>>(dw, db);
    gather_kernel<<<NT, 128>>>(routed);
}